// round 5
// baseline (speedup 1.0000x reference)
#include <cuda_runtime.h>
#include <math.h>

// ---------------- problem constants ----------------
#define BB    2
#define SS    1024
#define TT    2048           // B*S tokens
#define DD    1024
#define HH    16
#define KVHN  4
#define HDIM  64
#define EE    8
#define TOPK  2
#define FF    2048
#define QKV_LD 1536          // H*HD + 2*KV*HD
#define NASSIGN (TT*TOPK)

// ---------------- scratch (device globals; no allocs allowed) ----------------
__device__ float g_xn  [TT*DD];          // rmsnorm output (reused for both norms)
__device__ float g_qkv [TT*QKV_LD];      // fused qkv projection
__device__ float g_attn[TT*HH*HDIM];     // attention output pre-Wo
__device__ float g_h1  [TT*DD];          // residual after attention block
__device__ float g_wqkv[DD*QKV_LD];      // packed [D][1536] qkv weight
__device__ float g_t1  [NASSIGN*FF];     // x@w1 per assignment
__device__ float g_hexp[NASSIGN*FF];     // silu(x@w1)*(x@w3)
__device__ float g_yexp[NASSIGN*DD];     // expert outputs (weight folded in)
__device__ float g_assign_w[NASSIGN];
__device__ int   g_tok_idx  [NASSIGN];   // token id per grouped assignment slot
__device__ int   g_tok_assign[NASSIGN];  // token -> its 2 assignment slots
__device__ int   g_tok_e[NASSIGN];
__device__ float g_tok_w[NASSIGN];
__device__ int   g_cnt[EE];
__device__ int   g_off[EE+1];
__device__ int   g_cur[EE];

// ---------------- tf32 helpers ----------------
__device__ __forceinline__ unsigned f2tf(float x) {
    unsigned u;
    asm("cvt.rna.tf32.f32 %0, %1;" : "=r"(u) : "f"(x));
    return u;
}

__device__ __forceinline__ void mma_tf32(float c[4],
    unsigned a0, unsigned a1, unsigned a2, unsigned a3,
    unsigned b0, unsigned b1)
{
    asm volatile(
        "mma.sync.aligned.m16n8k8.row.col.f32.tf32.tf32.f32 "
        "{%0,%1,%2,%3}, {%4,%5,%6,%7}, {%8,%9}, {%0,%1,%2,%3};"
        : "+f"(c[0]), "+f"(c[1]), "+f"(c[2]), "+f"(c[3])
        : "r"(a0), "r"(a1), "r"(a2), "r"(a3), "r"(b0), "r"(b1));
}

// ---------------- RMSNorm: one block per token ----------------
__global__ __launch_bounds__(256) void rmsnorm_kernel(
    const float* __restrict__ x, const float* __restrict__ w, float* __restrict__ y)
{
    int t = blockIdx.x;
    const float4* xr = (const float4*)(x + (size_t)t * DD);
    int i = threadIdx.x;                       // 256 threads * 4 = 1024
    float4 v = xr[i];
    float ss = v.x*v.x + v.y*v.y + v.z*v.z + v.w*v.w;
    #pragma unroll
    for (int o = 16; o; o >>= 1) ss += __shfl_xor_sync(0xffffffffu, ss, o);
    __shared__ float red[8];
    if ((threadIdx.x & 31) == 0) red[threadIdx.x >> 5] = ss;
    __syncthreads();
    float tot = 0.f;
    #pragma unroll
    for (int r = 0; r < 8; r++) tot += red[r];
    float inv = rsqrtf(tot * (1.0f / DD) + 1e-6f);
    const float4* wr = (const float4*)w;
    float4 wv = wr[i];
    float4 ov = make_float4(v.x*inv*wv.x, v.y*inv*wv.y, v.z*inv*wv.z, v.w*inv*wv.w);
    ((float4*)(y + (size_t)t * DD))[i] = ov;
}

// ---------------- pack qkv weights into [D][1536] ----------------
__global__ __launch_bounds__(256) void pack_qkv_kernel(
    const float* __restrict__ wq, const float* __restrict__ wk,
    const float* __restrict__ wv, float* __restrict__ out)
{
    int idx = blockIdx.x * 256 + threadIdx.x;   // D*1536 total
    int d = idx / QKV_LD;
    int j = idx - d * QKV_LD;
    float v;
    if (j < 1024)       v = wq[d * 1024 + j];
    else if (j < 1280)  v = wk[d * 256 + (j - 1024)];
    else                v = wv[d * 256 + (j - 1280)];
    out[idx] = v;
}

// ---------------- tf32 tensor-core GEMM (128x128x32 block, 8 warps) ----------------
// MODE: 0 = plain C[M,N]=A@B ; 1 = grouped + row-gather (A rows via g_tok_idx)
//       2 = grouped, rows direct (A already in grouped order)
// EPI : 0 = none ; 1 = +resid ; 2 = silu(epi_src)*acc ; 3 = acc*rowscale[row]
template<int MODE, int EPI>
__global__ __launch_bounds__(256) void gemm_tf32(
    const float* __restrict__ A, const float* __restrict__ B, float* __restrict__ C,
    int M, int N, int Kd, int lda, int ldb, int ldc,
    const float* __restrict__ epi_src, const float* __restrict__ rowscale,
    const float* __restrict__ resid)
{
    __shared__ unsigned As[128 * 36];   // [m][k] pad 4
    __shared__ unsigned Bs[32 * 136];   // [k][n] pad 8

    int tid = threadIdx.x;
    int n0 = blockIdx.x * 128;
    int m0 = blockIdx.y * 128;

    int Me = M;
    int rowbase = 0;
    const int* gidx = nullptr;
    if (MODE != 0) {
        int e = blockIdx.z;
        Me = g_cnt[e];
        if (m0 >= Me) return;
        rowbase = g_off[e];
        B += (size_t)e * (size_t)Kd * (size_t)ldb;
        if (MODE == 1) gidx = g_tok_idx + rowbase;
    }

    // loader indexing: A tile is 128x32 floats = 4096; 256 threads * 16 floats each
    int ar = tid >> 1;             // 0..127  A row in tile
    int ac = (tid & 1) * 16;       // A col base: thread covers ac..ac+15
    int bk = tid >> 3;             // 0..31   B row (k)
    int bn = (tid & 7) * 4;        // B col base; q adds *32

    bool avalid = (m0 + ar) < Me;
    const float* Arow = A;
    if (avalid) {
        long rr;
        if (MODE == 1)      rr = (long)gidx[m0 + ar];
        else if (MODE == 2) rr = (long)(rowbase + m0 + ar);
        else                rr = (long)(m0 + ar);
        Arow = A + (size_t)rr * lda;
    }
    const float* Bbase = B + (size_t)bk * ldb + n0 + bn;

    int warp = tid >> 5, lane = tid & 31;
    int wm = (warp >> 2) * 64;     // warp m offset (0 / 64)
    int wn = (warp & 3) * 32;      // warp n offset (0..96)
    int r  = lane >> 2;            // 0..7
    int cc = lane & 3;             // 0..3

    float acc[4][4][4];
    #pragma unroll
    for (int mf = 0; mf < 4; mf++)
        #pragma unroll
        for (int nf = 0; nf < 4; nf++)
            #pragma unroll
            for (int q = 0; q < 4; q++) acc[mf][nf][q] = 0.f;

    float4 av[4], bv[4];
    {   // prefetch first k-tile (A: 4 x float4 = 16 floats covering ac..ac+15)
        #pragma unroll
        for (int q = 0; q < 4; q++)
            av[q] = avalid ? *(const float4*)(Arow + ac + q * 4)
                           : make_float4(0.f, 0.f, 0.f, 0.f);
        #pragma unroll
        for (int q = 0; q < 4; q++)
            bv[q] = *(const float4*)(Bbase + q * 32);
    }

    for (int k0 = 0; k0 < Kd; k0 += 32) {
        __syncthreads();   // previous tile fully consumed
        {   // store current tile (cvt to tf32)
            #pragma unroll
            for (int q = 0; q < 4; q++) {
                unsigned* p = &As[ar * 36 + ac + q * 4];
                uint4 u = make_uint4(f2tf(av[q].x), f2tf(av[q].y), f2tf(av[q].z), f2tf(av[q].w));
                *(uint4*)p = u;
            }
            #pragma unroll
            for (int q = 0; q < 4; q++) {
                unsigned* p = &Bs[bk * 136 + bn + q * 32];
                uint4 u = make_uint4(f2tf(bv[q].x), f2tf(bv[q].y), f2tf(bv[q].z), f2tf(bv[q].w));
                *(uint4*)p = u;
            }
        }
        __syncthreads();

        if (k0 + 32 < Kd) {   // prefetch next tile (overlaps mma)
            #pragma unroll
            for (int q = 0; q < 4; q++)
                av[q] = avalid ? *(const float4*)(Arow + k0 + 32 + ac + q * 4)
                               : make_float4(0.f, 0.f, 0.f, 0.f);
            #pragma unroll
            for (int q = 0; q < 4; q++)
                bv[q] = *(const float4*)(Bbase + (size_t)(k0 + 32) * ldb + q * 32);
        }

        #pragma unroll
        for (int ks = 0; ks < 4; ks++) {
            int kb = ks * 8;
            unsigned a[4][4], b[4][2];
            #pragma unroll
            for (int mf = 0; mf < 4; mf++) {
                int mrow = wm + mf * 16 + r;
                a[mf][0] = As[mrow * 36 + kb + cc];
                a[mf][1] = As[(mrow + 8) * 36 + kb + cc];
                a[mf][2] = As[mrow * 36 + kb + cc + 4];
                a[mf][3] = As[(mrow + 8) * 36 + kb + cc + 4];
            }
            #pragma unroll
            for (int nf = 0; nf < 4; nf++) {
                int ncol = wn + nf * 8 + r;
                b[nf][0] = Bs[(kb + cc) * 136 + ncol];
                b[nf][1] = Bs[(kb + cc + 4) * 136 + ncol];
            }
            #pragma unroll
            for (int mf = 0; mf < 4; mf++)
                #pragma unroll
                for (int nf = 0; nf < 4; nf++)
                    mma_tf32(acc[mf][nf], a[mf][0], a[mf][1], a[mf][2], a[mf][3],
                             b[nf][0], b[nf][1]);
        }
    }

    // epilogue: thread owns rows (r, r+8), cols (2cc, 2cc+1) per frag
    #pragma unroll
    for (int mf = 0; mf < 4; mf++) {
        #pragma unroll
        for (int half = 0; half < 2; half++) {
            int m = m0 + wm + mf * 16 + r + half * 8;
            if (m >= Me) continue;
            int crow = (MODE == 0) ? m : (rowbase + m);
            float rsc = (EPI == 3) ? rowscale[crow] : 1.f;
            #pragma unroll
            for (int nf = 0; nf < 4; nf++) {
                int n = n0 + wn + nf * 8 + cc * 2;
                float v0 = acc[mf][nf][half * 2 + 0];
                float v1 = acc[mf][nf][half * 2 + 1];
                size_t off = (size_t)crow * ldc + n;
                if (EPI == 1) {
                    float2 rv = *(const float2*)(resid + off);
                    v0 += rv.x; v1 += rv.y;
                }
                if (EPI == 2) {
                    float2 uv = *(const float2*)(epi_src + off);
                    v0 *= uv.x / (1.f + expf(-uv.x));
                    v1 *= uv.y / (1.f + expf(-uv.y));
                }
                if (EPI == 3) { v0 *= rsc; v1 *= rsc; }
                *(float2*)(C + off) = make_float2(v0, v1);
            }
        }
    }
}

// ---------------- RoPE (in-place on g_qkv, q heads 0..15, k heads 16..19) ----------------
__global__ __launch_bounds__(256) void rope_kernel(const int* __restrict__ pos_ids)
{
    int idx = blockIdx.x * blockDim.x + threadIdx.x;
    if (idx >= TT * 20 * 32) return;
    int i  = idx & 31;
    int hh = (idx >> 5) % 20;
    int t  = idx / (20 * 32);
    float pos = (float)pos_ids[t];
    float inv_freq = expf(-(float)(2 * i) * (1.0f / 64.0f) * logf(10000.0f));
    float ang = pos * inv_freq;
    float s, c;
    sincosf(ang, &s, &c);
    size_t base = (size_t)t * QKV_LD + (hh < 16 ? hh * 64 : 1024 + (hh - 16) * 64);
    float x1 = g_qkv[base + i];
    float x2 = g_qkv[base + i + 32];
    g_qkv[base + i]      = x1 * c - x2 * s;
    g_qkv[base + i + 32] = x2 * c + x1 * s;
}

// ---------------- causal flash attention, 64x64 tiles (fp32 SIMT) ----------------
__global__ __launch_bounds__(256) void attn_kernel()
{
    __shared__ float Qt[64 * 64];   // [d][r], pre-scaled by 1/sqrt(HD)
    __shared__ float KP[64 * 64];   // K as [d][c], then reused as P [r][c]
    __shared__ float Vs[64 * 64];   // [j][d]

    int qt = blockIdx.x, h = blockIdx.y, b = blockIdx.z;
    int tid = threadIdx.x;
    int tx = tid & 15, ty = tid >> 4;
    int kvh = h >> 2;

    {   // load Q tile (transposed, scaled)
        int r  = tid >> 2;
        int c0 = (tid & 3) * 16;
        const float* qp = g_qkv + ((size_t)(b * SS + qt * 64 + r) * QKV_LD) + h * 64 + c0;
        #pragma unroll
        for (int q = 0; q < 4; q++) {
            float4 v = *(const float4*)(qp + q * 4);
            int d = c0 + q * 4;
            Qt[(d + 0) * 64 + r] = v.x * 0.125f;
            Qt[(d + 1) * 64 + r] = v.y * 0.125f;
            Qt[(d + 2) * 64 + r] = v.z * 0.125f;
            Qt[(d + 3) * 64 + r] = v.w * 0.125f;
        }
    }

    float o[4][4] = {};
    float mrow[4], lrow[4];
    #pragma unroll
    for (int i = 0; i < 4; i++) { mrow[i] = -1e30f; lrow[i] = 0.f; }

    for (int kt = 0; kt <= qt; kt++) {
        __syncthreads();
        {   // load K (transposed) and V tiles
            int r  = tid >> 2;
            int c0 = (tid & 3) * 16;
            const float* kp = g_qkv + ((size_t)(b * SS + kt * 64 + r) * QKV_LD) + 1024 + kvh * 64 + c0;
            const float* vp = kp + 256;
            #pragma unroll
            for (int q = 0; q < 4; q++) {
                float4 k4 = *(const float4*)(kp + q * 4);
                int d = c0 + q * 4;
                KP[(d + 0) * 64 + r] = k4.x;
                KP[(d + 1) * 64 + r] = k4.y;
                KP[(d + 2) * 64 + r] = k4.z;
                KP[(d + 3) * 64 + r] = k4.w;
                float4 v4 = *(const float4*)(vp + q * 4);
                *(float4*)&Vs[r * 64 + d] = v4;
            }
        }
        __syncthreads();

        float s[4][4] = {};
        #pragma unroll 16
        for (int d = 0; d < 64; d++) {
            float4 a4 = *(const float4*)&Qt[d * 64 + ty * 4];
            float4 b4 = *(const float4*)&KP[d * 64 + tx * 4];
            float a[4] = {a4.x, a4.y, a4.z, a4.w};
            float bb[4] = {b4.x, b4.y, b4.z, b4.w};
            #pragma unroll
            for (int i = 0; i < 4; i++)
                #pragma unroll
                for (int j = 0; j < 4; j++)
                    s[i][j] = fmaf(a[i], bb[j], s[i][j]);
        }

        if (kt == qt) {
            #pragma unroll
            for (int i = 0; i < 4; i++)
                #pragma unroll
                for (int j = 0; j < 4; j++)
                    if (tx * 4 + j > ty * 4 + i) s[i][j] = -1e30f;
        }

        #pragma unroll
        for (int i = 0; i < 4; i++) {
            float mx = fmaxf(fmaxf(s[i][0], s[i][1]), fmaxf(s[i][2], s[i][3]));
            #pragma unroll
            for (int off = 8; off; off >>= 1)
                mx = fmaxf(mx, __shfl_xor_sync(0xffffffffu, mx, off));
            float mnew = fmaxf(mrow[i], mx);
            float sc = expf(mrow[i] - mnew);
            float rs = 0.f;
            #pragma unroll
            for (int j = 0; j < 4; j++) {
                float p = expf(s[i][j] - mnew);
                s[i][j] = p; rs += p;
            }
            #pragma unroll
            for (int off = 8; off; off >>= 1)
                rs += __shfl_xor_sync(0xffffffffu, rs, off);
            lrow[i] = lrow[i] * sc + rs;
            mrow[i] = mnew;
            #pragma unroll
            for (int j = 0; j < 4; j++) o[i][j] *= sc;
        }

        __syncthreads();
        #pragma unroll
        for (int i = 0; i < 4; i++)
            *(float4*)&KP[(ty * 4 + i) * 64 + tx * 4] =
                make_float4(s[i][0], s[i][1], s[i][2], s[i][3]);
        __syncthreads();

        #pragma unroll 8
        for (int j = 0; j < 64; j++) {
            float4 v4 = *(const float4*)&Vs[j * 64 + tx * 4];
            float p0 = KP[(ty * 4 + 0) * 64 + j];
            float p1 = KP[(ty * 4 + 1) * 64 + j];
            float p2 = KP[(ty * 4 + 2) * 64 + j];
            float p3 = KP[(ty * 4 + 3) * 64 + j];
            o[0][0] += p0 * v4.x; o[0][1] += p0 * v4.y; o[0][2] += p0 * v4.z; o[0][3] += p0 * v4.w;
            o[1][0] += p1 * v4.x; o[1][1] += p1 * v4.y; o[1][2] += p1 * v4.z; o[1][3] += p1 * v4.w;
            o[2][0] += p2 * v4.x; o[2][1] += p2 * v4.y; o[2][2] += p2 * v4.z; o[2][3] += p2 * v4.w;
            o[3][0] += p3 * v4.x; o[3][1] += p3 * v4.y; o[3][2] += p3 * v4.z; o[3][3] += p3 * v4.w;
        }
    }

    #pragma unroll
    for (int i = 0; i < 4; i++) {
        float inv = 1.f / lrow[i];
        int row = b * SS + qt * 64 + ty * 4 + i;
        float* op = g_attn + (size_t)row * (HH * HDIM) + h * 64 + tx * 4;
        op[0] = o[i][0] * inv;
        op[1] = o[i][1] * inv;
        op[2] = o[i][2] * inv;
        op[3] = o[i][3] * inv;
    }
}

// ---------------- router: warp per token ----------------
__global__ __launch_bounds__(128) void router_kernel(
    const float* __restrict__ gate_w, float* __restrict__ gate_out)
{
    int t = (blockIdx.x * blockDim.x + threadIdx.x) >> 5;
    int lane = threadIdx.x & 31;
    if (t >= TT) return;
    const float* xr = g_xn + (size_t)t * DD;
    float acc[8] = {};
    for (int d = lane; d < DD; d += 32) {
        float xv = xr[d];
        const float4* g = (const float4*)(gate_w + (size_t)d * 8);
        float4 g0 = g[0], g1 = g[1];
        acc[0] += xv * g0.x; acc[1] += xv * g0.y; acc[2] += xv * g0.z; acc[3] += xv * g0.w;
        acc[4] += xv * g1.x; acc[5] += xv * g1.y; acc[6] += xv * g1.z; acc[7] += xv * g1.w;
    }
    #pragma unroll
    for (int e = 0; e < 8; e++)
        #pragma unroll
        for (int off = 16; off; off >>= 1)
            acc[e] += __shfl_xor_sync(0xffffffffu, acc[e], off);

    if (lane == 0) {
        float mx = acc[0];
        #pragma unroll
        for (int e = 1; e < 8; e++) mx = fmaxf(mx, acc[e]);
        float p[8], ps = 0.f;
        #pragma unroll
        for (int e = 0; e < 8; e++) { p[e] = expf(acc[e] - mx); ps += p[e]; }
        float inv = 1.f / ps;
        #pragma unroll
        for (int e = 0; e < 8; e++) {
            p[e] *= inv;
            gate_out[(size_t)t * EE + e] = p[e];
        }
        int e0 = 0;
        #pragma unroll
        for (int e = 1; e < 8; e++) if (p[e] > p[e0]) e0 = e;
        int e1 = (e0 == 0) ? 1 : 0;
        #pragma unroll
        for (int e = 0; e < 8; e++) if (e != e0 && p[e] > p[e1]) e1 = e;
        float s = p[e0] + p[e1];
        float w0 = p[e0] / s, w1 = p[e1] / s;
        g_tok_e[t * 2]     = e0; g_tok_e[t * 2 + 1] = e1;
        g_tok_w[t * 2]     = w0; g_tok_w[t * 2 + 1] = w1;
        atomicAdd(&g_cnt[e0], 1);
        atomicAdd(&g_cnt[e1], 1);
    }
}

__global__ void zero_cnt_kernel() {
    if (threadIdx.x < EE) g_cnt[threadIdx.x] = 0;
}

__global__ void scan_kernel() {
    if (threadIdx.x == 0) {
        int s = 0;
        for (int e = 0; e < EE; e++) { g_off[e] = s; g_cur[e] = s; s += g_cnt[e]; }
        g_off[EE] = s;
    }
}

__global__ __launch_bounds__(256) void scatter_kernel() {
    int t = blockIdx.x * blockDim.x + threadIdx.x;
    if (t >= TT) return;
    #pragma unroll
    for (int k = 0; k < TOPK; k++) {
        int e = g_tok_e[t * 2 + k];
        int p = atomicAdd(&g_cur[e], 1);
        g_tok_idx[p]  = t;
        g_assign_w[p] = g_tok_w[t * 2 + k];
        g_tok_assign[t * 2 + k] = p;
    }
}

// ---------------- final combine ----------------
__global__ __launch_bounds__(256) void combine_kernel(float* __restrict__ out)
{
    int idx = blockIdx.x * blockDim.x + threadIdx.x;
    int t = idx >> 10;
    int d = idx & 1023;
    int a0 = g_tok_assign[t * 2];
    int a1 = g_tok_assign[t * 2 + 1];
    out[idx] = g_h1[idx] + g_yexp[(size_t)a0 * DD + d] + g_yexp[(size_t)a1 * DD + d];
}

// ---------------- launch ----------------
extern "C" void kernel_launch(void* const* d_in, const int* in_sizes, int n_in,
                              void* d_out, int out_size)
{
    const float* hidden = (const float*)d_in[0];
    const int*   pos    = (const int*)  d_in[1];
    const float* ln1    = (const float*)d_in[3];
    const float* ln2    = (const float*)d_in[4];
    const float* wq     = (const float*)d_in[5];
    const float* wk     = (const float*)d_in[6];
    const float* wv     = (const float*)d_in[7];
    const float* wo     = (const float*)d_in[8];
    const float* gate_w = (const float*)d_in[9];
    const float* w1     = (const float*)d_in[10];
    const float* w3     = (const float*)d_in[11];
    const float* w2     = (const float*)d_in[12];

    float* out      = (float*)d_out;
    float* gate_out = out + (size_t)TT * DD;

    float *p_xn, *p_qkv, *p_attn, *p_h1, *p_t1, *p_hexp, *p_yexp, *p_aw, *p_wqkv;
    cudaGetSymbolAddress((void**)&p_xn,   g_xn);
    cudaGetSymbolAddress((void**)&p_qkv,  g_qkv);
    cudaGetSymbolAddress((void**)&p_attn, g_attn);
    cudaGetSymbolAddress((void**)&p_h1,   g_h1);
    cudaGetSymbolAddress((void**)&p_t1,   g_t1);
    cudaGetSymbolAddress((void**)&p_hexp, g_hexp);
    cudaGetSymbolAddress((void**)&p_yexp, g_yexp);
    cudaGetSymbolAddress((void**)&p_aw,   g_assign_w);
    cudaGetSymbolAddress((void**)&p_wqkv, g_wqkv);

    // 0) pack qkv weights
    pack_qkv_kernel<<<(DD * QKV_LD) / 256, 256>>>(wq, wk, wv, p_wqkv);

    // 1) rmsnorm1
    rmsnorm_kernel<<<TT, 256>>>(hidden, ln1, p_xn);

    // 2) fused QKV projection (tf32 tensor cores)
    gemm_tf32<0,0><<<dim3(QKV_LD/128, TT/128), 256>>>(
        p_xn, p_wqkv, p_qkv, TT, QKV_LD, DD, DD, QKV_LD, QKV_LD, nullptr, nullptr, nullptr);

    // 3) RoPE on q and k
    rope_kernel<<<(TT * 20 * 32) / 256, 256>>>(pos);

    // 4) causal attention
    attn_kernel<<<dim3(SS/64, HH, BB), 256>>>();

    // 5) output projection + residual
    gemm_tf32<0,1><<<dim3(DD/128, TT/128), 256>>>(
        p_attn, wo, p_h1, TT, DD, HH*HDIM, HH*HDIM, DD, DD, nullptr, nullptr, hidden);

    // 6) rmsnorm2
    rmsnorm_kernel<<<TT, 256>>>(p_h1, ln2, p_xn);

    // 7) routing
    zero_cnt_kernel<<<1, 32>>>();
    router_kernel<<<TT/4, 128>>>(gate_w, gate_out);
    scan_kernel<<<1, 1>>>();
    scatter_kernel<<<TT/256, 256>>>();

    // 8) MoE grouped GEMMs (grid.y covers worst-case 4096 rows / 128)
    gemm_tf32<1,0><<<dim3(FF/128, 32, EE), 256>>>(
        p_xn, w1, p_t1, 0, FF, DD, DD, FF, FF, nullptr, nullptr, nullptr);
    gemm_tf32<1,2><<<dim3(FF/128, 32, EE), 256>>>(
        p_xn, w3, p_hexp, 0, FF, DD, DD, FF, FF, p_t1, nullptr, nullptr);
    gemm_tf32<2,3><<<dim3(DD/128, 32, EE), 256>>>(
        p_hexp, w2, p_yexp, 0, DD, FF, FF, DD, DD, nullptr, p_aw, nullptr);

    // 9) combine
    combine_kernel<<<(TT * DD) / 256, 256>>>(out);
}

// round 6
// speedup vs baseline: 1.1468x; 1.1468x over previous
#include <cuda_runtime.h>
#include <math.h>

// ---------------- problem constants ----------------
#define BB    2
#define SS    1024
#define TT    2048           // B*S tokens
#define DD    1024
#define HH    16
#define KVHN  4
#define HDIM  64
#define EE    8
#define TOPK  2
#define FF    2048
#define QKV_LD 1536          // H*HD + 2*KV*HD
#define NASSIGN (TT*TOPK)

// ---------------- scratch (device globals; no allocs allowed) ----------------
__device__ float g_xn  [TT*DD];          // rmsnorm output (reused for both norms)
__device__ float g_qkv [TT*QKV_LD];      // fused qkv projection
__device__ float g_attn[TT*HH*HDIM];     // attention output pre-Wo
__device__ float g_h1  [TT*DD];          // residual after attention block
__device__ float g_wqkv[DD*QKV_LD];      // packed [D][1536] qkv weight
__device__ float g_t1  [NASSIGN*FF];     // x@w1 per assignment
__device__ float g_hexp[NASSIGN*FF];     // silu(x@w1)*(x@w3)
__device__ float g_yexp[NASSIGN*DD];     // expert outputs (weight folded in)
__device__ float g_assign_w[NASSIGN];
__device__ int   g_tok_idx  [NASSIGN];   // token id per grouped assignment slot
__device__ int   g_tok_assign[NASSIGN];  // token -> its 2 assignment slots
__device__ int   g_tok_e[NASSIGN];
__device__ float g_tok_w[NASSIGN];
__device__ int   g_cnt[EE];
__device__ int   g_off[EE+1];
__device__ int   g_cur[EE];

// ---------------- tf32 helpers ----------------
__device__ __forceinline__ unsigned f2tf(float x) {
    unsigned u;
    asm("cvt.rna.tf32.f32 %0, %1;" : "=r"(u) : "f"(x));
    return u;
}

__device__ __forceinline__ void mma_tf32(float c[4],
    unsigned a0, unsigned a1, unsigned a2, unsigned a3,
    unsigned b0, unsigned b1)
{
    asm volatile(
        "mma.sync.aligned.m16n8k8.row.col.f32.tf32.tf32.f32 "
        "{%0,%1,%2,%3}, {%4,%5,%6,%7}, {%8,%9}, {%0,%1,%2,%3};"
        : "+f"(c[0]), "+f"(c[1]), "+f"(c[2]), "+f"(c[3])
        : "r"(a0), "r"(a1), "r"(a2), "r"(a3), "r"(b0), "r"(b1));
}

// ---------------- RMSNorm: one block per token ----------------
__global__ __launch_bounds__(256) void rmsnorm_kernel(
    const float* __restrict__ x, const float* __restrict__ w, float* __restrict__ y)
{
    int t = blockIdx.x;
    const float4* xr = (const float4*)(x + (size_t)t * DD);
    int i = threadIdx.x;                       // 256 threads * 4 = 1024
    float4 v = xr[i];
    float ss = v.x*v.x + v.y*v.y + v.z*v.z + v.w*v.w;
    #pragma unroll
    for (int o = 16; o; o >>= 1) ss += __shfl_xor_sync(0xffffffffu, ss, o);
    __shared__ float red[8];
    if ((threadIdx.x & 31) == 0) red[threadIdx.x >> 5] = ss;
    __syncthreads();
    float tot = 0.f;
    #pragma unroll
    for (int r = 0; r < 8; r++) tot += red[r];
    float inv = rsqrtf(tot * (1.0f / DD) + 1e-6f);
    const float4* wr = (const float4*)w;
    float4 wv = wr[i];
    float4 ov = make_float4(v.x*inv*wv.x, v.y*inv*wv.y, v.z*inv*wv.z, v.w*inv*wv.w);
    ((float4*)(y + (size_t)t * DD))[i] = ov;
}

// ---------------- pack qkv weights into [D][1536] ----------------
__global__ __launch_bounds__(256) void pack_qkv_kernel(
    const float* __restrict__ wq, const float* __restrict__ wk,
    const float* __restrict__ wv, float* __restrict__ out)
{
    int idx = blockIdx.x * 256 + threadIdx.x;   // D*1536 total
    int d = idx / QKV_LD;
    int j = idx - d * QKV_LD;
    float v;
    if (j < 1024)       v = wq[d * 1024 + j];
    else if (j < 1280)  v = wk[d * 256 + (j - 1024)];
    else                v = wv[d * 256 + (j - 1280)];
    out[idx] = v;
}

// ---------------- tf32 tensor-core GEMM (128x128x32 block, 8 warps) ----------------
// MODE: 0 = plain C[M,N]=A@B ; 1 = grouped + row-gather (A rows via g_tok_idx)
//       2 = grouped, rows direct (A already in grouped order)
// EPI : 0 = none ; 1 = +resid ; 2 = silu(epi_src)*acc ; 3 = acc*rowscale[row]
template<int MODE, int EPI>
__global__ __launch_bounds__(256) void gemm_tf32(
    const float* __restrict__ A, const float* __restrict__ B, float* __restrict__ C,
    int M, int N, int Kd, int lda, int ldb, int ldc,
    const float* __restrict__ epi_src, const float* __restrict__ rowscale,
    const float* __restrict__ resid)
{
    __shared__ unsigned As[128 * 36];   // [m][k] pad 4
    __shared__ unsigned Bs[32 * 136];   // [k][n] pad 8

    int tid = threadIdx.x;
    int n0 = blockIdx.x * 128;
    int m0 = blockIdx.y * 128;

    int Me = M;
    int rowbase = 0;
    const int* gidx = nullptr;
    if (MODE != 0) {
        int e = blockIdx.z;
        Me = g_cnt[e];
        if (m0 >= Me) return;
        rowbase = g_off[e];
        B += (size_t)e * (size_t)Kd * (size_t)ldb;
        if (MODE == 1) gidx = g_tok_idx + rowbase;
    }

    // loader indexing: A tile is 128x32 floats = 4096; 256 threads * 16 floats each
    int ar = tid >> 1;             // 0..127  A row in tile
    int ac = (tid & 1) * 16;       // A col base: thread covers ac..ac+15
    int bk = tid >> 3;             // 0..31   B row (k)
    int bn = (tid & 7) * 4;        // B col base; q adds *32

    bool avalid = (m0 + ar) < Me;
    const float* Arow = A;
    if (avalid) {
        long rr;
        if (MODE == 1)      rr = (long)gidx[m0 + ar];
        else if (MODE == 2) rr = (long)(rowbase + m0 + ar);
        else                rr = (long)(m0 + ar);
        Arow = A + (size_t)rr * lda;
    }
    const float* Bbase = B + (size_t)bk * ldb + n0 + bn;

    int warp = tid >> 5, lane = tid & 31;
    int wm = (warp >> 2) * 64;     // warp m offset (0 / 64)
    int wn = (warp & 3) * 32;      // warp n offset (0..96)
    int r  = lane >> 2;            // 0..7
    int cc = lane & 3;             // 0..3

    float acc[4][4][4];
    #pragma unroll
    for (int mf = 0; mf < 4; mf++)
        #pragma unroll
        for (int nf = 0; nf < 4; nf++)
            #pragma unroll
            for (int q = 0; q < 4; q++) acc[mf][nf][q] = 0.f;

    float4 av[4], bv[4];
    {   // prefetch first k-tile (A: 4 x float4 = 16 floats covering ac..ac+15)
        #pragma unroll
        for (int q = 0; q < 4; q++)
            av[q] = avalid ? *(const float4*)(Arow + ac + q * 4)
                           : make_float4(0.f, 0.f, 0.f, 0.f);
        #pragma unroll
        for (int q = 0; q < 4; q++)
            bv[q] = *(const float4*)(Bbase + q * 32);
    }

    for (int k0 = 0; k0 < Kd; k0 += 32) {
        __syncthreads();   // previous tile fully consumed
        {   // store current tile (cvt to tf32)
            #pragma unroll
            for (int q = 0; q < 4; q++) {
                unsigned* p = &As[ar * 36 + ac + q * 4];
                uint4 u = make_uint4(f2tf(av[q].x), f2tf(av[q].y), f2tf(av[q].z), f2tf(av[q].w));
                *(uint4*)p = u;
            }
            #pragma unroll
            for (int q = 0; q < 4; q++) {
                unsigned* p = &Bs[bk * 136 + bn + q * 32];
                uint4 u = make_uint4(f2tf(bv[q].x), f2tf(bv[q].y), f2tf(bv[q].z), f2tf(bv[q].w));
                *(uint4*)p = u;
            }
        }
        __syncthreads();

        if (k0 + 32 < Kd) {   // prefetch next tile (overlaps mma)
            #pragma unroll
            for (int q = 0; q < 4; q++)
                av[q] = avalid ? *(const float4*)(Arow + k0 + 32 + ac + q * 4)
                               : make_float4(0.f, 0.f, 0.f, 0.f);
            #pragma unroll
            for (int q = 0; q < 4; q++)
                bv[q] = *(const float4*)(Bbase + (size_t)(k0 + 32) * ldb + q * 32);
        }

        #pragma unroll
        for (int ks = 0; ks < 4; ks++) {
            int kb = ks * 8;
            unsigned a[4][4], b[4][2];
            #pragma unroll
            for (int mf = 0; mf < 4; mf++) {
                int mrow = wm + mf * 16 + r;
                a[mf][0] = As[mrow * 36 + kb + cc];
                a[mf][1] = As[(mrow + 8) * 36 + kb + cc];
                a[mf][2] = As[mrow * 36 + kb + cc + 4];
                a[mf][3] = As[(mrow + 8) * 36 + kb + cc + 4];
            }
            #pragma unroll
            for (int nf = 0; nf < 4; nf++) {
                int ncol = wn + nf * 8 + r;
                b[nf][0] = Bs[(kb + cc) * 136 + ncol];
                b[nf][1] = Bs[(kb + cc + 4) * 136 + ncol];
            }
            #pragma unroll
            for (int mf = 0; mf < 4; mf++)
                #pragma unroll
                for (int nf = 0; nf < 4; nf++)
                    mma_tf32(acc[mf][nf], a[mf][0], a[mf][1], a[mf][2], a[mf][3],
                             b[nf][0], b[nf][1]);
        }
    }

    // epilogue: thread owns rows (r, r+8), cols (2cc, 2cc+1) per frag
    #pragma unroll
    for (int mf = 0; mf < 4; mf++) {
        #pragma unroll
        for (int half = 0; half < 2; half++) {
            int m = m0 + wm + mf * 16 + r + half * 8;
            if (m >= Me) continue;
            int crow = (MODE == 0) ? m : (rowbase + m);
            float rsc = (EPI == 3) ? rowscale[crow] : 1.f;
            #pragma unroll
            for (int nf = 0; nf < 4; nf++) {
                int n = n0 + wn + nf * 8 + cc * 2;
                float v0 = acc[mf][nf][half * 2 + 0];
                float v1 = acc[mf][nf][half * 2 + 1];
                size_t off = (size_t)crow * ldc + n;
                if (EPI == 1) {
                    float2 rv = *(const float2*)(resid + off);
                    v0 += rv.x; v1 += rv.y;
                }
                if (EPI == 2) {
                    float2 uv = *(const float2*)(epi_src + off);
                    v0 *= uv.x / (1.f + expf(-uv.x));
                    v1 *= uv.y / (1.f + expf(-uv.y));
                }
                if (EPI == 3) { v0 *= rsc; v1 *= rsc; }
                *(float2*)(C + off) = make_float2(v0, v1);
            }
        }
    }
}

// ---------------- RoPE (in-place on g_qkv, q heads 0..15, k heads 16..19) ----------------
__global__ __launch_bounds__(256) void rope_kernel(const int* __restrict__ pos_ids)
{
    int idx = blockIdx.x * blockDim.x + threadIdx.x;
    if (idx >= TT * 20 * 32) return;
    int i  = idx & 31;
    int hh = (idx >> 5) % 20;
    int t  = idx / (20 * 32);
    float pos = (float)pos_ids[t];
    float inv_freq = expf(-(float)(2 * i) * (1.0f / 64.0f) * logf(10000.0f));
    float ang = pos * inv_freq;
    float s, c;
    sincosf(ang, &s, &c);
    size_t base = (size_t)t * QKV_LD + (hh < 16 ? hh * 64 : 1024 + (hh - 16) * 64);
    float x1 = g_qkv[base + i];
    float x2 = g_qkv[base + i + 32];
    g_qkv[base + i]      = x1 * c - x2 * s;
    g_qkv[base + i + 32] = x2 * c + x1 * s;
}

// ---------------- causal flash attention, tf32 tensor cores ----------------
// Block: 128 q-rows x (kv tiles of 64). 8 warps, each warp owns 16 q-rows.
// Q fragments in registers; K^T [d][kv] and V [kv][d] tf32 in smem (stride 72);
// P converted acc->A-frag layout via quad shuffles (no smem round trip).
#define ATT_STRIDE 72
__global__ __launch_bounds__(256) void attn_kernel()
{
    __shared__ unsigned smem_u[128 * ATT_STRIDE];   // Q staging; then Ks | Vs
    unsigned* Ks = smem_u;                          // [d][kv] 64x72
    unsigned* Vs = smem_u + 64 * ATT_STRIDE;        // [kv][d] 64x72

    int qt = blockIdx.x, h = blockIdx.y, b = blockIdx.z;
    int tid  = threadIdx.x;
    int warp = tid >> 5, lane = tid & 31;
    int r  = lane >> 2;       // 0..7
    int cc = lane & 3;        // 0..3
    int q0 = qt * 128;
    int kvh = h >> 2;

    // ---- stage Q tile into smem (scaled), coalesced ----
    {
        int row = tid >> 1;               // 0..127
        int c0  = (tid & 1) * 32;         // 0 / 32
        const float* qp = g_qkv + ((size_t)(b * SS + q0 + row) * QKV_LD) + h * 64 + c0;
        unsigned* dst = &smem_u[row * ATT_STRIDE + c0];
        #pragma unroll
        for (int q = 0; q < 8; q++) {
            float4 v = *(const float4*)(qp + q * 4);
            dst[q*4+0] = f2tf(v.x * 0.125f);
            dst[q*4+1] = f2tf(v.y * 0.125f);
            dst[q*4+2] = f2tf(v.z * 0.125f);
            dst[q*4+3] = f2tf(v.w * 0.125f);
        }
    }
    __syncthreads();

    // ---- Q fragments to registers: qa[ks][0..3] ----
    unsigned qa[8][4];
    {
        int row0 = warp * 16 + r;
        #pragma unroll
        for (int ks = 0; ks < 8; ks++) {
            int kb = ks * 8;
            qa[ks][0] = smem_u[ row0      * ATT_STRIDE + kb + cc];
            qa[ks][1] = smem_u[(row0 + 8) * ATT_STRIDE + kb + cc];
            qa[ks][2] = smem_u[ row0      * ATT_STRIDE + kb + cc + 4];
            qa[ks][3] = smem_u[(row0 + 8) * ATT_STRIDE + kb + cc + 4];
        }
    }

    float oacc[8][4];
    #pragma unroll
    for (int nf = 0; nf < 8; nf++)
        #pragma unroll
        for (int q = 0; q < 4; q++) oacc[nf][q] = 0.f;
    float m0v = -1e30f, m1v = -1e30f, l0 = 0.f, l1 = 0.f;

    int row_g0 = q0 + warp * 16 + r;       // global q row (slot 0/1)
    int row_g1 = row_g0 + 8;               // slots 2/3
    int ktmax = 2 * qt + 1;

    for (int kt = 0; kt <= ktmax; kt++) {
        __syncthreads();   // previous tile consumed (also Q staging on first iter)
        {   // load K (transposed) and V tiles, cvt tf32
            int j  = tid >> 2;            // 0..63 kv row
            int d0 = (tid & 3) * 16;
            const float* kp = g_qkv + ((size_t)(b * SS + kt * 64 + j) * QKV_LD) + 1024 + kvh * 64 + d0;
            const float* vp = kp + 256;
            #pragma unroll
            for (int q = 0; q < 4; q++) {
                float4 k4 = *(const float4*)(kp + q * 4);
                int d = d0 + q * 4;
                Ks[(d + 0) * ATT_STRIDE + j] = f2tf(k4.x);
                Ks[(d + 1) * ATT_STRIDE + j] = f2tf(k4.y);
                Ks[(d + 2) * ATT_STRIDE + j] = f2tf(k4.z);
                Ks[(d + 3) * ATT_STRIDE + j] = f2tf(k4.w);
                float4 v4 = *(const float4*)(vp + q * 4);
                uint4 u = make_uint4(f2tf(v4.x), f2tf(v4.y), f2tf(v4.z), f2tf(v4.w));
                *(uint4*)&Vs[j * ATT_STRIDE + d] = u;
            }
        }
        __syncthreads();

        // ---- S = Q K^T ----
        float s[8][4];
        #pragma unroll
        for (int nf = 0; nf < 8; nf++)
            #pragma unroll
            for (int q = 0; q < 4; q++) s[nf][q] = 0.f;

        #pragma unroll
        for (int ks = 0; ks < 8; ks++) {
            int kb = ks * 8;
            unsigned bfr[8][2];
            #pragma unroll
            for (int nf = 0; nf < 8; nf++) {
                int ncol = nf * 8 + r;
                bfr[nf][0] = Ks[(kb + cc)     * ATT_STRIDE + ncol];
                bfr[nf][1] = Ks[(kb + cc + 4) * ATT_STRIDE + ncol];
            }
            #pragma unroll
            for (int nf = 0; nf < 8; nf++)
                mma_tf32(s[nf], qa[ks][0], qa[ks][1], qa[ks][2], qa[ks][3],
                         bfr[nf][0], bfr[nf][1]);
        }

        // ---- causal mask (only near-diagonal tiles) ----
        if (kt >= 2 * qt) {
            #pragma unroll
            for (int nf = 0; nf < 8; nf++) {
                int c0g = kt * 64 + nf * 8 + cc * 2;
                if (c0g     > row_g0) s[nf][0] = -1e30f;
                if (c0g + 1 > row_g0) s[nf][1] = -1e30f;
                if (c0g     > row_g1) s[nf][2] = -1e30f;
                if (c0g + 1 > row_g1) s[nf][3] = -1e30f;
            }
        }

        // ---- online softmax (rows r and r+8; stats across quad lanes) ----
        float mx0 = -1e30f, mx1 = -1e30f;
        #pragma unroll
        for (int nf = 0; nf < 8; nf++) {
            mx0 = fmaxf(mx0, fmaxf(s[nf][0], s[nf][1]));
            mx1 = fmaxf(mx1, fmaxf(s[nf][2], s[nf][3]));
        }
        #pragma unroll
        for (int off = 1; off <= 2; off <<= 1) {
            mx0 = fmaxf(mx0, __shfl_xor_sync(0xffffffffu, mx0, off));
            mx1 = fmaxf(mx1, __shfl_xor_sync(0xffffffffu, mx1, off));
        }
        float mn0 = fmaxf(m0v, mx0), mn1 = fmaxf(m1v, mx1);
        float sc0 = __expf(m0v - mn0), sc1 = __expf(m1v - mn1);
        float rs0 = 0.f, rs1 = 0.f;
        #pragma unroll
        for (int nf = 0; nf < 8; nf++) {
            s[nf][0] = __expf(s[nf][0] - mn0);
            s[nf][1] = __expf(s[nf][1] - mn0);
            s[nf][2] = __expf(s[nf][2] - mn1);
            s[nf][3] = __expf(s[nf][3] - mn1);
            rs0 += s[nf][0] + s[nf][1];
            rs1 += s[nf][2] + s[nf][3];
        }
        #pragma unroll
        for (int off = 1; off <= 2; off <<= 1) {
            rs0 += __shfl_xor_sync(0xffffffffu, rs0, off);
            rs1 += __shfl_xor_sync(0xffffffffu, rs1, off);
        }
        l0 = l0 * sc0 + rs0;  m0v = mn0;
        l1 = l1 * sc1 + rs1;  m1v = mn1;
        #pragma unroll
        for (int nf = 0; nf < 8; nf++) {
            oacc[nf][0] *= sc0; oacc[nf][1] *= sc0;
            oacc[nf][2] *= sc1; oacc[nf][3] *= sc1;
        }

        // ---- P acc-layout -> A-frag layout via quad shuffles, then O += P V ----
        int src1 = (lane & ~3) | (cc >> 1);
        int src2 = src1 + 2;
        int sel  = cc & 1;
        #pragma unroll
        for (int ks = 0; ks < 8; ks++) {
            float v0 = __shfl_sync(0xffffffffu, s[ks][0], src1);
            float v1 = __shfl_sync(0xffffffffu, s[ks][1], src1);
            float v2 = __shfl_sync(0xffffffffu, s[ks][2], src1);
            float v3 = __shfl_sync(0xffffffffu, s[ks][3], src1);
            float w0 = __shfl_sync(0xffffffffu, s[ks][0], src2);
            float w1 = __shfl_sync(0xffffffffu, s[ks][1], src2);
            float w2 = __shfl_sync(0xffffffffu, s[ks][2], src2);
            float w3 = __shfl_sync(0xffffffffu, s[ks][3], src2);
            unsigned a0 = f2tf(sel ? v1 : v0);
            unsigned a1 = f2tf(sel ? v3 : v2);
            unsigned a2 = f2tf(sel ? w1 : w0);
            unsigned a3 = f2tf(sel ? w3 : w2);
            int kb = ks * 8;
            unsigned bfr[8][2];
            #pragma unroll
            for (int nf = 0; nf < 8; nf++) {
                int ncol = nf * 8 + r;
                bfr[nf][0] = Vs[(kb + cc)     * ATT_STRIDE + ncol];
                bfr[nf][1] = Vs[(kb + cc + 4) * ATT_STRIDE + ncol];
            }
            #pragma unroll
            for (int nf = 0; nf < 8; nf++)
                mma_tf32(oacc[nf], a0, a1, a2, a3, bfr[nf][0], bfr[nf][1]);
        }
    }

    // ---- epilogue: O /= l ----
    float inv0 = 1.f / l0, inv1 = 1.f / l1;
    float* op0 = g_attn + (size_t)(b * SS + row_g0) * (HH * HDIM) + h * 64;
    float* op1 = g_attn + (size_t)(b * SS + row_g1) * (HH * HDIM) + h * 64;
    #pragma unroll
    for (int nf = 0; nf < 8; nf++) {
        int n = nf * 8 + cc * 2;
        *(float2*)(op0 + n) = make_float2(oacc[nf][0] * inv0, oacc[nf][1] * inv0);
        *(float2*)(op1 + n) = make_float2(oacc[nf][2] * inv1, oacc[nf][3] * inv1);
    }
}

// ---------------- router: warp per token ----------------
__global__ __launch_bounds__(128) void router_kernel(
    const float* __restrict__ gate_w, float* __restrict__ gate_out)
{
    int t = (blockIdx.x * blockDim.x + threadIdx.x) >> 5;
    int lane = threadIdx.x & 31;
    if (t >= TT) return;
    const float* xr = g_xn + (size_t)t * DD;
    float acc[8] = {};
    for (int d = lane; d < DD; d += 32) {
        float xv = xr[d];
        const float4* g = (const float4*)(gate_w + (size_t)d * 8);
        float4 g0 = g[0], g1 = g[1];
        acc[0] += xv * g0.x; acc[1] += xv * g0.y; acc[2] += xv * g0.z; acc[3] += xv * g0.w;
        acc[4] += xv * g1.x; acc[5] += xv * g1.y; acc[6] += xv * g1.z; acc[7] += xv * g1.w;
    }
    #pragma unroll
    for (int e = 0; e < 8; e++)
        #pragma unroll
        for (int off = 16; off; off >>= 1)
            acc[e] += __shfl_xor_sync(0xffffffffu, acc[e], off);

    if (lane == 0) {
        float mx = acc[0];
        #pragma unroll
        for (int e = 1; e < 8; e++) mx = fmaxf(mx, acc[e]);
        float p[8], ps = 0.f;
        #pragma unroll
        for (int e = 0; e < 8; e++) { p[e] = expf(acc[e] - mx); ps += p[e]; }
        float inv = 1.f / ps;
        #pragma unroll
        for (int e = 0; e < 8; e++) {
            p[e] *= inv;
            gate_out[(size_t)t * EE + e] = p[e];
        }
        int e0 = 0;
        #pragma unroll
        for (int e = 1; e < 8; e++) if (p[e] > p[e0]) e0 = e;
        int e1 = (e0 == 0) ? 1 : 0;
        #pragma unroll
        for (int e = 0; e < 8; e++) if (e != e0 && p[e] > p[e1]) e1 = e;
        float s = p[e0] + p[e1];
        float w0 = p[e0] / s, w1 = p[e1] / s;
        g_tok_e[t * 2]     = e0; g_tok_e[t * 2 + 1] = e1;
        g_tok_w[t * 2]     = w0; g_tok_w[t * 2 + 1] = w1;
        atomicAdd(&g_cnt[e0], 1);
        atomicAdd(&g_cnt[e1], 1);
    }
}

__global__ void zero_cnt_kernel() {
    if (threadIdx.x < EE) g_cnt[threadIdx.x] = 0;
}

__global__ void scan_kernel() {
    if (threadIdx.x == 0) {
        int s = 0;
        for (int e = 0; e < EE; e++) { g_off[e] = s; g_cur[e] = s; s += g_cnt[e]; }
        g_off[EE] = s;
    }
}

__global__ __launch_bounds__(256) void scatter_kernel() {
    int t = blockIdx.x * blockDim.x + threadIdx.x;
    if (t >= TT) return;
    #pragma unroll
    for (int k = 0; k < TOPK; k++) {
        int e = g_tok_e[t * 2 + k];
        int p = atomicAdd(&g_cur[e], 1);
        g_tok_idx[p]  = t;
        g_assign_w[p] = g_tok_w[t * 2 + k];
        g_tok_assign[t * 2 + k] = p;
    }
}

// ---------------- final combine ----------------
__global__ __launch_bounds__(256) void combine_kernel(float* __restrict__ out)
{
    int idx = blockIdx.x * blockDim.x + threadIdx.x;
    int t = idx >> 10;
    int d = idx & 1023;
    int a0 = g_tok_assign[t * 2];
    int a1 = g_tok_assign[t * 2 + 1];
    out[idx] = g_h1[idx] + g_yexp[(size_t)a0 * DD + d] + g_yexp[(size_t)a1 * DD + d];
}

// ---------------- launch ----------------
extern "C" void kernel_launch(void* const* d_in, const int* in_sizes, int n_in,
                              void* d_out, int out_size)
{
    const float* hidden = (const float*)d_in[0];
    const int*   pos    = (const int*)  d_in[1];
    const float* ln1    = (const float*)d_in[3];
    const float* ln2    = (const float*)d_in[4];
    const float* wq     = (const float*)d_in[5];
    const float* wk     = (const float*)d_in[6];
    const float* wv     = (const float*)d_in[7];
    const float* wo     = (const float*)d_in[8];
    const float* gate_w = (const float*)d_in[9];
    const float* w1     = (const float*)d_in[10];
    const float* w3     = (const float*)d_in[11];
    const float* w2     = (const float*)d_in[12];

    float* out      = (float*)d_out;
    float* gate_out = out + (size_t)TT * DD;

    float *p_xn, *p_qkv, *p_attn, *p_h1, *p_t1, *p_hexp, *p_yexp, *p_aw, *p_wqkv;
    cudaGetSymbolAddress((void**)&p_xn,   g_xn);
    cudaGetSymbolAddress((void**)&p_qkv,  g_qkv);
    cudaGetSymbolAddress((void**)&p_attn, g_attn);
    cudaGetSymbolAddress((void**)&p_h1,   g_h1);
    cudaGetSymbolAddress((void**)&p_t1,   g_t1);
    cudaGetSymbolAddress((void**)&p_hexp, g_hexp);
    cudaGetSymbolAddress((void**)&p_yexp, g_yexp);
    cudaGetSymbolAddress((void**)&p_aw,   g_assign_w);
    cudaGetSymbolAddress((void**)&p_wqkv, g_wqkv);

    // 0) pack qkv weights
    pack_qkv_kernel<<<(DD * QKV_LD) / 256, 256>>>(wq, wk, wv, p_wqkv);

    // 1) rmsnorm1
    rmsnorm_kernel<<<TT, 256>>>(hidden, ln1, p_xn);

    // 2) fused QKV projection (tf32 tensor cores)
    gemm_tf32<0,0><<<dim3(QKV_LD/128, TT/128), 256>>>(
        p_xn, p_wqkv, p_qkv, TT, QKV_LD, DD, DD, QKV_LD, QKV_LD, nullptr, nullptr, nullptr);

    // 3) RoPE on q and k
    rope_kernel<<<(TT * 20 * 32) / 256, 256>>>(pos);

    // 4) causal attention (tf32 tensor cores, 128-row q tiles)
    attn_kernel<<<dim3(SS/128, HH, BB), 256>>>();

    // 5) output projection + residual
    gemm_tf32<0,1><<<dim3(DD/128, TT/128), 256>>>(
        p_attn, wo, p_h1, TT, DD, HH*HDIM, HH*HDIM, DD, DD, nullptr, nullptr, hidden);

    // 6) rmsnorm2
    rmsnorm_kernel<<<TT, 256>>>(p_h1, ln2, p_xn);

    // 7) routing
    zero_cnt_kernel<<<1, 32>>>();
    router_kernel<<<TT/4, 128>>>(gate_w, gate_out);
    scan_kernel<<<1, 1>>>();
    scatter_kernel<<<TT/256, 256>>>();

    // 8) MoE grouped GEMMs (grid.y covers worst-case 4096 rows / 128)
    gemm_tf32<1,0><<<dim3(FF/128, 32, EE), 256>>>(
        p_xn, w1, p_t1, 0, FF, DD, DD, FF, FF, nullptr, nullptr, nullptr);
    gemm_tf32<1,2><<<dim3(FF/128, 32, EE), 256>>>(
        p_xn, w3, p_hexp, 0, FF, DD, DD, FF, FF, p_t1, nullptr, nullptr);
    gemm_tf32<2,3><<<dim3(DD/128, 32, EE), 256>>>(
        p_hexp, w2, p_yexp, 0, DD, FF, FF, DD, DD, nullptr, p_aw, nullptr);

    // 9) combine
    combine_kernel<<<(TT * DD) / 256, 256>>>(out);
}